// round 15
// baseline (speedup 1.0000x reference)
#include <cuda_runtime.h>
#include <cuda_bf16.h>
#include <cstdint>

#define RELS 3
#define F 128
#define NMAX 50000
#define EMAX 800000
#define WSLOTS 64

// ---------------- scratch (static device globals; no allocation) ----------------
__device__ float    g_XW[(size_t)RELS * NMAX * F];   // [r][n][f]  76.8 MB
__device__ float    g_H[(size_t)NMAX * F];
__device__ uint32_t g_XHI[(size_t)NMAX * 64];
__device__ uint32_t g_XLO[(size_t)NMAX * 64];
__device__ uint32_t g_WHI[2 * RELS * 128 * 64];
__device__ uint32_t g_WLO[2 * RELS * 128 * 64];
__device__ float    g_NQ[NMAX * RELS];
__device__ float    g_NK[NMAX * RELS];
__device__ float    g_NQ2[NMAX * RELS];
__device__ float    g_NK2[NMAX * RELS];
__device__ float    g_EX[EMAX];
__device__ float    g_WQ[2 * RELS * F];
__device__ float    g_WK[2 * RELS * F];
__device__ float    g_CE[2];
__device__ int   g_CNT[NMAX];
__device__ int   g_ROWPTR[NMAX + 1];
__device__ int   g_PART[NMAX];
__device__ int   g_BSUM[1024];
__device__ int4  g_EDGE[EMAX];                       // {nkidx, rowidx, sea_bits, 0}

__device__ __forceinline__ uint32_t pack_split_hi(float x, float y) {
    __nv_bfloat16 hx = __float2bfloat16_rn(x);
    __nv_bfloat16 hy = __float2bfloat16_rn(y);
    return ((uint32_t)*(uint16_t*)&hy << 16) | (uint32_t)*(uint16_t*)&hx;
}
__device__ __forceinline__ uint32_t pack_split_lo(float x, float y) {
    __nv_bfloat16 hx = __float2bfloat16_rn(x);
    __nv_bfloat16 hy = __float2bfloat16_rn(y);
    __nv_bfloat16 lx = __float2bfloat16_rn(x - __bfloat162float(hx));
    __nv_bfloat16 ly = __float2bfloat16_rn(y - __bfloat162float(hy));
    return ((uint32_t)*(uint16_t*)&ly << 16) | (uint32_t)*(uint16_t*)&lx;
}

// -------- setup: prep (wq/wk/ce) + prepw (W split) + zero_cnt, fused --------
#define N_PREP (4 * RELS * F + 2)
#define N_PREPW (2 * RELS * 64 * 128)
__global__ void setup_kernel(const float* __restrict__ w1, const float* __restrict__ q1,
                             const float* __restrict__ k1,
                             const float* __restrict__ w2, const float* __restrict__ q2,
                             const float* __restrict__ k2,
                             const float* __restrict__ we1, const float* __restrict__ e1,
                             const float* __restrict__ we2, const float* __restrict__ e2,
                             int Nn) {
    int idx = blockIdx.x * blockDim.x + threadIdx.x;
    if (idx < 4 * RELS * F) {
        int which = idx / (RELS * F);
        int rem   = idx % (RELS * F);
        const float* w = (which < 2) ? w1 : w2;
        const float* v = (which == 0) ? q1 : (which == 1) ? k1 : (which == 2) ? q2 : k2;
        const float* row = w + (size_t)rem * F;
        float s = 0.f;
        #pragma unroll 8
        for (int o = 0; o < F; o++) s += row[o] * v[o];
        float* d = (which == 0) ? g_WQ
                 : (which == 1) ? g_WK
                 : (which == 2) ? (g_WQ + RELS * F)
                 : (g_WK + RELS * F);
        d[rem] = s;
    } else if (idx == 4 * RELS * F) {
        float s = 0.f;
        for (int o = 0; o < F; o++) s += we1[o] * e1[o];
        g_CE[0] = s;
    } else if (idx == 4 * RELS * F + 1) {
        float s = 0.f;
        for (int o = 0; o < F; o++) s += we2[o] * e2[o];
        g_CE[1] = s;
    } else if (idx < N_PREP + N_PREPW) {
        int j = idx - N_PREP;
        int n     = j & 127;
        int p     = (j >> 7) & 63;
        int r     = (j >> 13) % RELS;
        int layer = j / (RELS * 64 * 128);
        const float* W = (layer == 0) ? w1 : w2;
        const float* Wr = W + (size_t)r * F * F;
        float vx = Wr[(size_t)(2 * p) * F + n];
        float vy = Wr[(size_t)(2 * p + 1) * F + n];
        size_t o = ((size_t)(layer * RELS + r) * 128 + n) * 64 + p;
        g_WHI[o] = pack_split_hi(vx, vy);
        g_WLO[o] = pack_split_lo(vx, vy);
    } else if (idx < N_PREP + N_PREPW + Nn) {
        g_CNT[idx - N_PREP - N_PREPW] = 0;
    }
}

// ---------------- CSR build ----------------
__global__ void hist_kernel(const int* __restrict__ dst, int Ecnt) {
    int e = blockIdx.x * blockDim.x + threadIdx.x;
    if (e < Ecnt) atomicAdd(&g_CNT[dst[e]], 1);
}
__global__ void scan1_kernel(int Nn) {
    __shared__ int sh[256];
    int i = blockIdx.x * 256 + threadIdx.x;
    int v = (i < Nn) ? g_CNT[i] : 0;
    sh[threadIdx.x] = v;
    __syncthreads();
    #pragma unroll
    for (int off = 1; off < 256; off <<= 1) {
        int t = (threadIdx.x >= off) ? sh[threadIdx.x - off] : 0;
        __syncthreads();
        sh[threadIdx.x] += t;
        __syncthreads();
    }
    if (i < Nn) g_PART[i] = sh[threadIdx.x] - v;
    if (threadIdx.x == 255) g_BSUM[blockIdx.x] = sh[255];
}
__global__ void scan2_kernel(int nb) {
    __shared__ int sh[1024];
    int v = (threadIdx.x < nb) ? g_BSUM[threadIdx.x] : 0;
    sh[threadIdx.x] = v;
    __syncthreads();
    #pragma unroll
    for (int off = 1; off < 1024; off <<= 1) {
        int t = (threadIdx.x >= off) ? sh[threadIdx.x - off] : 0;
        __syncthreads();
        sh[threadIdx.x] += t;
        __syncthreads();
    }
    if (threadIdx.x < nb) g_BSUM[threadIdx.x] = sh[threadIdx.x] - v;
}
__global__ void scan3_kernel(int Nn, int Ecnt) {
    int i = blockIdx.x * blockDim.x + threadIdx.x;
    if (i < Nn) {
        g_ROWPTR[i] = g_PART[i] + g_BSUM[i >> 8];
        g_CNT[i] = 0;
    }
    if (i == Nn) g_ROWPTR[Nn] = Ecnt;
}
__global__ void scatter_kernel(const int* __restrict__ src, const int* __restrict__ dst,
                               const int* __restrict__ et, const float* __restrict__ ea,
                               int Ecnt, int Nn) {
    int e = blockIdx.x * blockDim.x + threadIdx.x;
    if (e >= Ecnt) return;
    int d = dst[e];
    int pos = g_ROWPTR[d] + atomicAdd(&g_CNT[d], 1);
    int s = src[e], t = et[e];
    g_EDGE[pos] = make_int4(s * RELS + t, t * Nn + s, __float_as_int(ea[e]), 0);
}

// ------- fused: x -> bf16 hi/lo split + layer-1 attention logits; warp per node -------
__global__ __launch_bounds__(256) void split_nqnk_kernel(const float* __restrict__ xin, int Nn) {
    __shared__ float swq[RELS * F];
    __shared__ float swk[RELS * F];
    for (int i = threadIdx.x; i < RELS * F; i += blockDim.x) {
        swq[i] = g_WQ[i];
        swk[i] = g_WK[i];
    }
    __syncthreads();

    int warp = (blockIdx.x * blockDim.x + threadIdx.x) >> 5;
    int lane = threadIdx.x & 31;
    if (warp >= Nn) return;

    float4 v = ((const float4*)(xin + (size_t)warp * F))[lane];

    uint32_t* xh = g_XHI + (size_t)warp * 64;
    uint32_t* xl = g_XLO + (size_t)warp * 64;
    xh[lane * 2]     = pack_split_hi(v.x, v.y);
    xh[lane * 2 + 1] = pack_split_hi(v.z, v.w);
    xl[lane * 2]     = pack_split_lo(v.x, v.y);
    xl[lane * 2 + 1] = pack_split_lo(v.z, v.w);

    #pragma unroll
    for (int r = 0; r < RELS; r++) {
        const float4 q4 = ((const float4*)(swq + r * F))[lane];
        const float4 k4 = ((const float4*)(swk + r * F))[lane];
        float sq = v.x * q4.x + v.y * q4.y + v.z * q4.z + v.w * q4.w;
        float sk = v.x * k4.x + v.y * k4.y + v.z * k4.z + v.w * k4.w;
        #pragma unroll
        for (int off = 16; off; off >>= 1) {
            sq += __shfl_down_sync(0xffffffffu, sq, off);
            sk += __shfl_down_sync(0xffffffffu, sk, off);
        }
        if (lane == 0) {
            g_NQ[warp * RELS + r] = sq;
            g_NK[warp * RELS + r] = sk;
        }
    }
}

// == mma.sync bf16 GEMM: M=64 tile, 8 warps (2x4), ldmatrix, 2 CTAs/SM ==
#define APITCH 68
#define ATILE_WORDS (64 * APITCH)
#define BTILE_WORDS (128 * APITCH)
#define GEMM_SMEM_TOTAL ((2 * ATILE_WORDS + 2 * BTILE_WORDS) * 4)   // 104,448 B

__device__ __forceinline__ void mma16816(float* d, const uint32_t* a, const uint32_t* b) {
    asm volatile("mma.sync.aligned.m16n8k16.row.col.f32.bf16.bf16.f32 "
                 "{%0,%1,%2,%3}, {%4,%5,%6,%7}, {%8,%9}, {%0,%1,%2,%3};"
                 : "+f"(d[0]), "+f"(d[1]), "+f"(d[2]), "+f"(d[3])
                 : "r"(a[0]), "r"(a[1]), "r"(a[2]), "r"(a[3]), "r"(b[0]), "r"(b[1]));
}
__device__ __forceinline__ void ldsm_x4(uint32_t* r, uint32_t saddr) {
    asm volatile("ldmatrix.sync.aligned.m8n8.x4.shared.b16 {%0,%1,%2,%3}, [%4];"
                 : "=r"(r[0]), "=r"(r[1]), "=r"(r[2]), "=r"(r[3]) : "r"(saddr));
}
__device__ __forceinline__ void cp16(uint32_t dst_smem, const void* src) {
    asm volatile("cp.async.cg.shared.global [%0], [%1], 16;" :: "r"(dst_smem), "l"(src) : "memory");
}
__device__ __forceinline__ void cp_commit() {
    asm volatile("cp.async.commit_group;" ::: "memory");
}
template <int N>
__device__ __forceinline__ void cp_wait() {
    asm volatile("cp.async.wait_group %0;" :: "n"(N) : "memory");
}

__global__ __launch_bounds__(256) void gemm_mma_kernel(int layer, int Nn) {
    extern __shared__ uint32_t smem[];
    uint32_t* sAhi = smem;
    uint32_t* sAlo = smem + ATILE_WORDS;

    int rowBase = blockIdx.x * 64;
    int tid = threadIdx.x;
    uint32_t sbase = (uint32_t)__cvta_generic_to_shared(smem);

    // ---- A tiles (64 rows): loaded ONCE, reused for all 3 relations ----
    for (int idx = tid; idx < 64 * 64; idx += 256) {
        int row = idx >> 6;
        int pair = idx & 63;
        int grow = rowBase + row;
        uint32_t hi = 0, lo = 0;
        if (grow < Nn) {
            hi = g_XHI[(size_t)grow * 64 + pair];
            lo = g_XLO[(size_t)grow * 64 + pair];
        }
        sAhi[row * APITCH + pair] = hi;
        sAlo[row * APITCH + pair] = lo;
    }

    int wid = tid >> 5;
    int lane = tid & 31;
    int warpM = wid & 1;           // 2 bands of 32 rows
    int warpN = wid >> 1;          // 4 bands of 32 cols
    int g = lane >> 2;
    int tig = lane & 3;
    int rw = lane & 7;
    int quad = lane >> 3;

    uint32_t aoff = (uint32_t)((warpM * 32 + rw + (quad & 1) * 8) * APITCH + (quad >> 1) * 4);
    uint32_t boff = (uint32_t)((warpN * 32 + rw + (quad >> 1) * 8) * APITCH + (quad & 1) * 4);
    uint32_t bbase = (uint32_t)(2 * ATILE_WORDS);

    for (int r = 0; r < RELS; r++) {
        __syncthreads();   // readers done with B[r-1] (and A visible on r=0)
        // fill B[r] via cp.async (single buffer; cross-CTA overlap hides latency)
        {
            const uint32_t* wh = g_WHI + (size_t)(layer * RELS + r) * 128 * 64;
            const uint32_t* wl = g_WLO + (size_t)(layer * RELS + r) * 128 * 64;
            uint32_t bhi = sbase + bbase * 4;
            uint32_t blo = sbase + (bbase + BTILE_WORDS) * 4;
            #pragma unroll
            for (int it = 0; it < 8; it++) {
                int c = tid + it * 256;      // 16B-chunk index 0..2047
                int n = c >> 4;
                int p4 = (c & 15) * 4;
                uint32_t doff = (uint32_t)(n * APITCH + p4) * 4;
                cp16(bhi + doff, wh + n * 64 + p4);
                cp16(blo + doff, wl + n * 64 + p4);
            }
            cp_commit();
            cp_wait<0>();
        }
        __syncthreads();

        float acc[2][4][4];
        #pragma unroll
        for (int mt = 0; mt < 2; mt++)
            #pragma unroll
            for (int nt = 0; nt < 4; nt++)
                #pragma unroll
                for (int c = 0; c < 4; c++) acc[mt][nt][c] = 0.f;

        #pragma unroll
        for (int ks = 0; ks < 8; ks++) {
            uint32_t kw = (uint32_t)(ks * 8) * 4;
            uint32_t ah[2][4], al[2][4];
            ldsm_x4(ah[0], sbase + aoff * 4 + kw);
            ldsm_x4(ah[1], sbase + (aoff + 16 * APITCH) * 4 + kw);
            ldsm_x4(al[0], sbase + (ATILE_WORDS + aoff) * 4 + kw);
            ldsm_x4(al[1], sbase + (ATILE_WORDS + aoff + 16 * APITCH) * 4 + kw);
            uint32_t bh[4][2], bl[4][2];
            #pragma unroll
            for (int np = 0; np < 2; np++) {
                uint32_t r4[4];
                ldsm_x4(r4, sbase + (bbase + boff + np * 16 * APITCH) * 4 + kw);
                bh[np * 2][0] = r4[0]; bh[np * 2][1] = r4[1];
                bh[np * 2 + 1][0] = r4[2]; bh[np * 2 + 1][1] = r4[3];
                ldsm_x4(r4, sbase + (bbase + BTILE_WORDS + boff + np * 16 * APITCH) * 4 + kw);
                bl[np * 2][0] = r4[0]; bl[np * 2][1] = r4[1];
                bl[np * 2 + 1][0] = r4[2]; bl[np * 2 + 1][1] = r4[3];
            }
            #pragma unroll
            for (int mt = 0; mt < 2; mt++)
                #pragma unroll
                for (int nt = 0; nt < 4; nt++) {
                    mma16816(acc[mt][nt], ah[mt], bh[nt]);
                    mma16816(acc[mt][nt], ah[mt], bl[nt]);
                    mma16816(acc[mt][nt], al[mt], bh[nt]);
                }
        }

        float* outp = g_XW + (size_t)r * Nn * F;
        #pragma unroll
        for (int mt = 0; mt < 2; mt++) {
            int row0 = rowBase + warpM * 32 + mt * 16 + g;
            int row1 = row0 + 8;
            #pragma unroll
            for (int nt = 0; nt < 4; nt++) {
                int col = warpN * 32 + nt * 8 + tig * 2;
                if (row0 < Nn)
                    *(float2*)(outp + (size_t)row0 * F + col) = make_float2(acc[mt][nt][0], acc[mt][nt][1]);
                if (row1 < Nn)
                    *(float2*)(outp + (size_t)row1 * F + col) = make_float2(acc[mt][nt][2], acc[mt][nt][3]);
            }
        }
    }
}

// -------- fused softmax + aggregate + bias(+relu) [+ next-layer split & logits] --------
__global__ __launch_bounds__(256) void fused_agg_kernel(float* __restrict__ outp,
                                                        const float* __restrict__ bias,
                                                        int layer, int relu, int donext,
                                                        int use2, int Nn) {
    __shared__ float swq[RELS * F];
    __shared__ float swk[RELS * F];
    __shared__ int   srow[8][WSLOTS];
    __shared__ float sex[8][WSLOTS];
    if (donext) {
        const float* WQ = g_WQ + (layer + 1) * RELS * F;
        const float* WK = g_WK + (layer + 1) * RELS * F;
        for (int i = threadIdx.x; i < RELS * F; i += blockDim.x) {
            swq[i] = WQ[i];
            swk[i] = WK[i];
        }
        __syncthreads();
    }

    int wslot = threadIdx.x >> 5;
    int node = (blockIdx.x * blockDim.x + threadIdx.x) >> 5;
    int lane = threadIdx.x & 31;
    if (node >= Nn) return;

    const float* NQ = use2 ? g_NQ2 : g_NQ;
    const float* NK = use2 ? g_NK2 : g_NK;

    int start = g_ROWPTR[node];
    int end   = g_ROWPTR[node + 1];
    float ce  = g_CE[layer];
    float nq0 = NQ[node * RELS + 0];
    float nq1 = NQ[node * RELS + 1];
    float nq2 = NQ[node * RELS + 2];

    float denom = 0.f;
    for (int i = start + lane; i < end; i += 32) {
        int4 e = g_EDGE[i];
        int t = e.x - (e.x / RELS) * RELS;
        float nq = (t == 0) ? nq0 : (t == 1) ? nq1 : nq2;
        float a = nq + NK[e.x] + ce * __int_as_float(e.z);
        a = (a > 0.f) ? a : 0.2f * a;
        float ex = expf(a);
        int k = i - start;
        if (k < WSLOTS) {
            srow[wslot][k] = e.y;
            sex[wslot][k]  = ex;
        } else {
            g_EX[i] = ex;
        }
        denom += ex;
    }
    #pragma unroll
    for (int off = 16; off; off >>= 1)
        denom += __shfl_xor_sync(0xffffffffu, denom, off);
    float inv = 1.f / (denom + 1e-16f);
    __syncwarp();

    int deg = end - start;
    int m = deg < WSLOTS ? deg : WSLOTS;
    float4 acc = make_float4(0.f, 0.f, 0.f, 0.f);
    int k = 0;
    for (; k + 7 < m; k += 8) {
        float at[8];
        float4 v[8];
        #pragma unroll
        for (int u = 0; u < 8; u++) {
            at[u] = sex[wslot][k + u] * inv;
            v[u] = ((const float4*)(g_XW + (size_t)srow[wslot][k + u] * F))[lane];
        }
        #pragma unroll
        for (int u = 0; u < 8; u++) {
            acc.x += at[u] * v[u].x;
            acc.y += at[u] * v[u].y;
            acc.z += at[u] * v[u].z;
            acc.w += at[u] * v[u].w;
        }
    }
    for (; k + 3 < m; k += 4) {
        float at[4];
        float4 v[4];
        #pragma unroll
        for (int u = 0; u < 4; u++) {
            at[u] = sex[wslot][k + u] * inv;
            v[u] = ((const float4*)(g_XW + (size_t)srow[wslot][k + u] * F))[lane];
        }
        #pragma unroll
        for (int u = 0; u < 4; u++) {
            acc.x += at[u] * v[u].x;
            acc.y += at[u] * v[u].y;
            acc.z += at[u] * v[u].z;
            acc.w += at[u] * v[u].w;
        }
    }
    for (; k < m; k++) {
        float at = sex[wslot][k] * inv;
        float4 v = ((const float4*)(g_XW + (size_t)srow[wslot][k] * F))[lane];
        acc.x += at * v.x;
        acc.y += at * v.y;
        acc.z += at * v.z;
        acc.w += at * v.w;
    }
    for (int i = start + WSLOTS; i < end; i++) {
        float at = g_EX[i] * inv;
        int r0 = ((const int*)g_EDGE)[4 * i + 1];
        float4 v = ((const float4*)(g_XW + (size_t)r0 * F))[lane];
        acc.x += at * v.x;
        acc.y += at * v.y;
        acc.z += at * v.z;
        acc.w += at * v.w;
    }

    const float4 b = *(const float4*)(bias + lane * 4);
    acc.x += b.x; acc.y += b.y; acc.z += b.z; acc.w += b.w;
    if (relu) {
        acc.x = acc.x > 0.f ? acc.x : 0.f;
        acc.y = acc.y > 0.f ? acc.y : 0.f;
        acc.z = acc.z > 0.f ? acc.z : 0.f;
        acc.w = acc.w > 0.f ? acc.w : 0.f;
    }
    *(float4*)(outp + (size_t)node * F + lane * 4) = acc;

    if (donext) {
        uint32_t* xh = g_XHI + (size_t)node * 64;
        uint32_t* xl = g_XLO + (size_t)node * 64;
        xh[lane * 2]     = pack_split_hi(acc.x, acc.y);
        xh[lane * 2 + 1] = pack_split_hi(acc.z, acc.w);
        xl[lane * 2]     = pack_split_lo(acc.x, acc.y);
        xl[lane * 2 + 1] = pack_split_lo(acc.z, acc.w);

        #pragma unroll
        for (int r = 0; r < RELS; r++) {
            const float4 q4 = ((const float4*)(swq + r * F))[lane];
            const float4 k4 = ((const float4*)(swk + r * F))[lane];
            float sq = acc.x * q4.x + acc.y * q4.y + acc.z * q4.z + acc.w * q4.w;
            float sk = acc.x * k4.x + acc.y * k4.y + acc.z * k4.z + acc.w * k4.w;
            #pragma unroll
            for (int off = 16; off; off >>= 1) {
                sq += __shfl_down_sync(0xffffffffu, sq, off);
                sk += __shfl_down_sync(0xffffffffu, sk, off);
            }
            if (lane == 0) {
                g_NQ2[node * RELS + r] = sq;
                g_NK2[node * RELS + r] = sk;
            }
        }
    }
}

// ---------------- launch ----------------
extern "C" void kernel_launch(void* const* d_in, const int* in_sizes, int n_in,
                              void* d_out, int out_size) {
    const float* x   = (const float*)d_in[0];
    const int*   ei  = (const int*)d_in[1];
    const int*   et  = (const int*)d_in[2];
    const float* ea  = (const float*)d_in[3];
    const float* w1  = (const float*)d_in[4];
    const float* q1  = (const float*)d_in[5];
    const float* k1  = (const float*)d_in[6];
    const float* e1  = (const float*)d_in[7];
    const float* we1 = (const float*)d_in[8];
    const float* b1  = (const float*)d_in[9];
    const float* w2  = (const float*)d_in[10];
    const float* q2  = (const float*)d_in[11];
    const float* k2  = (const float*)d_in[12];
    const float* e2  = (const float*)d_in[13];
    const float* we2 = (const float*)d_in[14];
    const float* b2  = (const float*)d_in[15];

    int Nn = in_sizes[0] / F;
    int Ecnt = in_sizes[2];
    const int* srcp = ei;
    const int* dstp = ei + Ecnt;
    float* outp = (float*)d_out;

    int setupThreads = N_PREP + N_PREPW + Nn;
    int edgeBlocks  = (Ecnt + 255) / 256;
    int scanBlocks  = (Nn + 255) / 256;
    int gemmBlocks  = (Nn + 63) / 64;
    int warpNodeBlk = (Nn + 7) / 8;

    cudaFuncSetAttribute(gemm_mma_kernel, cudaFuncAttributeMaxDynamicSharedMemorySize,
                         GEMM_SMEM_TOTAL);

    void* hptr = nullptr;
    cudaGetSymbolAddress(&hptr, g_H);

    setup_kernel<<<(setupThreads + 255) / 256, 256>>>(w1, q1, k1, w2, q2, k2,
                                                      we1, e1, we2, e2, Nn);         // 0
    split_nqnk_kernel<<<warpNodeBlk, 256>>>(x, Nn);                                  // 1
    hist_kernel<<<edgeBlocks, 256>>>(dstp, Ecnt);                                    // 2
    gemm_mma_kernel<<<gemmBlocks, 256, GEMM_SMEM_TOTAL>>>(0, Nn);                    // 3 (ncu window)
    scan1_kernel<<<scanBlocks, 256>>>(Nn);                                           // 4
    scan2_kernel<<<1, 1024>>>(scanBlocks);                                           // 5
    scan3_kernel<<<(Nn + 256) / 256, 256>>>(Nn, Ecnt);                               // 6
    scatter_kernel<<<edgeBlocks, 256>>>(srcp, dstp, et, ea, Ecnt, Nn);               // 7
    fused_agg_kernel<<<warpNodeBlk, 256>>>((float*)hptr, b1, 0, 1, 1, 0, Nn);        // 8
    gemm_mma_kernel<<<gemmBlocks, 256, GEMM_SMEM_TOTAL>>>(1, Nn);                    // 9
    fused_agg_kernel<<<warpNodeBlk, 256>>>(outp, b2, 1, 0, 0, 1, Nn);                // 10

    (void)n_in; (void)out_size;
}

// round 16
// speedup vs baseline: 1.1005x; 1.1005x over previous
#include <cuda_runtime.h>
#include <cuda_bf16.h>
#include <cuda_fp16.h>
#include <cstdint>

#define RELS 3
#define F 128
#define NMAX 50000
#define EMAX 800000
#define WSLOTS 64

// ---------------- scratch (static device globals; no allocation) ----------------
__device__ __half   g_XWH[(size_t)RELS * NMAX * F];  // [r][n][f] fp16, 38.4 MB (L2-resident)
__device__ float    g_H[(size_t)NMAX * F];
__device__ uint32_t g_XHI[(size_t)NMAX * 64];
__device__ uint32_t g_XLO[(size_t)NMAX * 64];
__device__ uint32_t g_WHI[2 * RELS * 128 * 64];
__device__ uint32_t g_WLO[2 * RELS * 128 * 64];
__device__ float    g_NQ[NMAX * RELS];
__device__ float    g_NK[NMAX * RELS];
__device__ float    g_NQ2[NMAX * RELS];
__device__ float    g_NK2[NMAX * RELS];
__device__ float    g_EX[EMAX];
__device__ float    g_WQ[2 * RELS * F];
__device__ float    g_WK[2 * RELS * F];
__device__ float    g_CE[2];
__device__ int   g_CNT[NMAX];
__device__ int   g_ROWPTR[NMAX + 1];
__device__ int   g_PART[NMAX];
__device__ int   g_BSUM[1024];
__device__ int4  g_EDGE[EMAX];                       // {nkidx, rowidx, sea_bits, 0}

__device__ __forceinline__ uint32_t pack_split_hi(float x, float y) {
    __nv_bfloat16 hx = __float2bfloat16_rn(x);
    __nv_bfloat16 hy = __float2bfloat16_rn(y);
    return ((uint32_t)*(uint16_t*)&hy << 16) | (uint32_t)*(uint16_t*)&hx;
}
__device__ __forceinline__ uint32_t pack_split_lo(float x, float y) {
    __nv_bfloat16 hx = __float2bfloat16_rn(x);
    __nv_bfloat16 hy = __float2bfloat16_rn(y);
    __nv_bfloat16 lx = __float2bfloat16_rn(x - __bfloat162float(hx));
    __nv_bfloat16 ly = __float2bfloat16_rn(y - __bfloat162float(hy));
    return ((uint32_t)*(uint16_t*)&ly << 16) | (uint32_t)*(uint16_t*)&lx;
}

// -------- setup: prep (wq/wk/ce) + prepw (W split) + zero_cnt, fused --------
#define N_PREP (4 * RELS * F + 2)
#define N_PREPW (2 * RELS * 64 * 128)
__global__ void setup_kernel(const float* __restrict__ w1, const float* __restrict__ q1,
                             const float* __restrict__ k1,
                             const float* __restrict__ w2, const float* __restrict__ q2,
                             const float* __restrict__ k2,
                             const float* __restrict__ we1, const float* __restrict__ e1,
                             const float* __restrict__ we2, const float* __restrict__ e2,
                             int Nn) {
    int idx = blockIdx.x * blockDim.x + threadIdx.x;
    if (idx < 4 * RELS * F) {
        int which = idx / (RELS * F);
        int rem   = idx % (RELS * F);
        const float* w = (which < 2) ? w1 : w2;
        const float* v = (which == 0) ? q1 : (which == 1) ? k1 : (which == 2) ? q2 : k2;
        const float* row = w + (size_t)rem * F;
        float s = 0.f;
        #pragma unroll 8
        for (int o = 0; o < F; o++) s += row[o] * v[o];
        float* d = (which == 0) ? g_WQ
                 : (which == 1) ? g_WK
                 : (which == 2) ? (g_WQ + RELS * F)
                 : (g_WK + RELS * F);
        d[rem] = s;
    } else if (idx == 4 * RELS * F) {
        float s = 0.f;
        for (int o = 0; o < F; o++) s += we1[o] * e1[o];
        g_CE[0] = s;
    } else if (idx == 4 * RELS * F + 1) {
        float s = 0.f;
        for (int o = 0; o < F; o++) s += we2[o] * e2[o];
        g_CE[1] = s;
    } else if (idx < N_PREP + N_PREPW) {
        int j = idx - N_PREP;
        int n     = j & 127;
        int p     = (j >> 7) & 63;
        int r     = (j >> 13) % RELS;
        int layer = j / (RELS * 64 * 128);
        const float* W = (layer == 0) ? w1 : w2;
        const float* Wr = W + (size_t)r * F * F;
        float vx = Wr[(size_t)(2 * p) * F + n];
        float vy = Wr[(size_t)(2 * p + 1) * F + n];
        size_t o = ((size_t)(layer * RELS + r) * 128 + n) * 64 + p;
        g_WHI[o] = pack_split_hi(vx, vy);
        g_WLO[o] = pack_split_lo(vx, vy);
    } else if (idx < N_PREP + N_PREPW + Nn) {
        g_CNT[idx - N_PREP - N_PREPW] = 0;
    }
}

// ---------------- CSR build ----------------
__global__ void hist_kernel(const int* __restrict__ dst, int Ecnt) {
    int e = blockIdx.x * blockDim.x + threadIdx.x;
    if (e < Ecnt) atomicAdd(&g_CNT[dst[e]], 1);
}
__global__ void scan1_kernel(int Nn) {
    __shared__ int sh[256];
    int i = blockIdx.x * 256 + threadIdx.x;
    int v = (i < Nn) ? g_CNT[i] : 0;
    sh[threadIdx.x] = v;
    __syncthreads();
    #pragma unroll
    for (int off = 1; off < 256; off <<= 1) {
        int t = (threadIdx.x >= off) ? sh[threadIdx.x - off] : 0;
        __syncthreads();
        sh[threadIdx.x] += t;
        __syncthreads();
    }
    if (i < Nn) g_PART[i] = sh[threadIdx.x] - v;
    if (threadIdx.x == 255) g_BSUM[blockIdx.x] = sh[255];
}
__global__ void scan2_kernel(int nb) {
    __shared__ int sh[1024];
    int v = (threadIdx.x < nb) ? g_BSUM[threadIdx.x] : 0;
    sh[threadIdx.x] = v;
    __syncthreads();
    #pragma unroll
    for (int off = 1; off < 1024; off <<= 1) {
        int t = (threadIdx.x >= off) ? sh[threadIdx.x - off] : 0;
        __syncthreads();
        sh[threadIdx.x] += t;
        __syncthreads();
    }
    if (threadIdx.x < nb) g_BSUM[threadIdx.x] = sh[threadIdx.x] - v;
}
__global__ void scan3_kernel(int Nn, int Ecnt) {
    int i = blockIdx.x * blockDim.x + threadIdx.x;
    if (i < Nn) {
        g_ROWPTR[i] = g_PART[i] + g_BSUM[i >> 8];
        g_CNT[i] = 0;
    }
    if (i == Nn) g_ROWPTR[Nn] = Ecnt;
}
__global__ void scatter_kernel(const int* __restrict__ src, const int* __restrict__ dst,
                               const int* __restrict__ et, const float* __restrict__ ea,
                               int Ecnt, int Nn) {
    int e = blockIdx.x * blockDim.x + threadIdx.x;
    if (e >= Ecnt) return;
    int d = dst[e];
    int pos = g_ROWPTR[d] + atomicAdd(&g_CNT[d], 1);
    int s = src[e], t = et[e];
    g_EDGE[pos] = make_int4(s * RELS + t, t * Nn + s, __float_as_int(ea[e]), 0);
}

// ------- fused: x -> bf16 hi/lo split + layer-1 attention logits; warp per node -------
__global__ __launch_bounds__(256) void split_nqnk_kernel(const float* __restrict__ xin, int Nn) {
    __shared__ float swq[RELS * F];
    __shared__ float swk[RELS * F];
    for (int i = threadIdx.x; i < RELS * F; i += blockDim.x) {
        swq[i] = g_WQ[i];
        swk[i] = g_WK[i];
    }
    __syncthreads();

    int warp = (blockIdx.x * blockDim.x + threadIdx.x) >> 5;
    int lane = threadIdx.x & 31;
    if (warp >= Nn) return;

    float4 v = ((const float4*)(xin + (size_t)warp * F))[lane];

    uint32_t* xh = g_XHI + (size_t)warp * 64;
    uint32_t* xl = g_XLO + (size_t)warp * 64;
    xh[lane * 2]     = pack_split_hi(v.x, v.y);
    xh[lane * 2 + 1] = pack_split_hi(v.z, v.w);
    xl[lane * 2]     = pack_split_lo(v.x, v.y);
    xl[lane * 2 + 1] = pack_split_lo(v.z, v.w);

    #pragma unroll
    for (int r = 0; r < RELS; r++) {
        const float4 q4 = ((const float4*)(swq + r * F))[lane];
        const float4 k4 = ((const float4*)(swk + r * F))[lane];
        float sq = v.x * q4.x + v.y * q4.y + v.z * q4.z + v.w * q4.w;
        float sk = v.x * k4.x + v.y * k4.y + v.z * k4.z + v.w * k4.w;
        #pragma unroll
        for (int off = 16; off; off >>= 1) {
            sq += __shfl_down_sync(0xffffffffu, sq, off);
            sk += __shfl_down_sync(0xffffffffu, sk, off);
        }
        if (lane == 0) {
            g_NQ[warp * RELS + r] = sq;
            g_NK[warp * RELS + r] = sk;
        }
    }
}

// == mma.sync bf16 GEMM (R14 config): M=128, 8 warps 32x64, ldmatrix, cp.async dbuf B ==
// fp16 epilogue: XW stored as __half.
#define APITCH 68
#define TILE_WORDS (128 * APITCH)
#define GEMM_SMEM_TOTAL (6 * TILE_WORDS * 4)     // A hi/lo + 2x (B hi/lo)

__device__ __forceinline__ void mma16816(float* d, const uint32_t* a, const uint32_t* b) {
    asm volatile("mma.sync.aligned.m16n8k16.row.col.f32.bf16.bf16.f32 "
                 "{%0,%1,%2,%3}, {%4,%5,%6,%7}, {%8,%9}, {%0,%1,%2,%3};"
                 : "+f"(d[0]), "+f"(d[1]), "+f"(d[2]), "+f"(d[3])
                 : "r"(a[0]), "r"(a[1]), "r"(a[2]), "r"(a[3]), "r"(b[0]), "r"(b[1]));
}
__device__ __forceinline__ void ldsm_x4(uint32_t* r, uint32_t saddr) {
    asm volatile("ldmatrix.sync.aligned.m8n8.x4.shared.b16 {%0,%1,%2,%3}, [%4];"
                 : "=r"(r[0]), "=r"(r[1]), "=r"(r[2]), "=r"(r[3]) : "r"(saddr));
}
__device__ __forceinline__ void cp16(uint32_t dst_smem, const void* src) {
    asm volatile("cp.async.cg.shared.global [%0], [%1], 16;" :: "r"(dst_smem), "l"(src) : "memory");
}
__device__ __forceinline__ void cp_commit() {
    asm volatile("cp.async.commit_group;" ::: "memory");
}
template <int N>
__device__ __forceinline__ void cp_wait() {
    asm volatile("cp.async.wait_group %0;" :: "n"(N) : "memory");
}

__global__ __launch_bounds__(256) void gemm_mma_kernel(int layer, int Nn) {
    extern __shared__ uint32_t smem[];
    uint32_t* sAhi = smem;
    uint32_t* sAlo = smem + TILE_WORDS;

    int rowBase = blockIdx.x * 128;
    int tid = threadIdx.x;
    uint32_t sbase = (uint32_t)__cvta_generic_to_shared(smem);

    // ---- A tiles: loaded ONCE, reused for all 3 relations ----
    for (int idx = tid; idx < 128 * 64; idx += 256) {
        int row = idx >> 6;
        int pair = idx & 63;
        int grow = rowBase + row;
        uint32_t hi = 0, lo = 0;
        if (grow < Nn) {
            hi = g_XHI[(size_t)grow * 64 + pair];
            lo = g_XLO[(size_t)grow * 64 + pair];
        }
        sAhi[row * APITCH + pair] = hi;
        sAlo[row * APITCH + pair] = lo;
    }

    // ---- prefetch B[r=0] into buf0 via cp.async ----
    {
        const uint32_t* wh = g_WHI + (size_t)(layer * RELS) * 128 * 64;
        const uint32_t* wl = g_WLO + (size_t)(layer * RELS) * 128 * 64;
        uint32_t bhi = sbase + (2 * TILE_WORDS) * 4;
        uint32_t blo = sbase + (3 * TILE_WORDS) * 4;
        #pragma unroll
        for (int it = 0; it < 8; it++) {
            int c = tid + it * 256;
            int n = c >> 4;
            int p4 = (c & 15) * 4;
            uint32_t doff = (uint32_t)(n * APITCH + p4) * 4;
            cp16(bhi + doff, wh + n * 64 + p4);
            cp16(blo + doff, wl + n * 64 + p4);
        }
        cp_commit();
    }

    int wid = tid >> 5;
    int lane = tid & 31;
    int warpM = wid & 3;
    int warpN = wid >> 2;
    int g = lane >> 2;
    int tig = lane & 3;
    int rw = lane & 7;
    int quad = lane >> 3;

    uint32_t aoff = (uint32_t)((warpM * 32 + rw + (quad & 1) * 8) * APITCH + (quad >> 1) * 4);
    uint32_t boff = (uint32_t)((warpN * 64 + rw + (quad >> 1) * 8) * APITCH + (quad & 1) * 4);

    for (int r = 0; r < RELS; r++) {
        __syncthreads();   // readers done with prefetch-target buffer; A visible on r=0
        if (r + 1 < RELS) {
            const uint32_t* wh = g_WHI + (size_t)(layer * RELS + r + 1) * 128 * 64;
            const uint32_t* wl = g_WLO + (size_t)(layer * RELS + r + 1) * 128 * 64;
            uint32_t bhi = sbase + (2 * TILE_WORDS + ((r + 1) & 1) * 2 * TILE_WORDS) * 4;
            uint32_t blo = bhi + TILE_WORDS * 4;
            #pragma unroll
            for (int it = 0; it < 8; it++) {
                int c = tid + it * 256;
                int n = c >> 4;
                int p4 = (c & 15) * 4;
                uint32_t doff = (uint32_t)(n * APITCH + p4) * 4;
                cp16(bhi + doff, wh + n * 64 + p4);
                cp16(blo + doff, wl + n * 64 + p4);
            }
            cp_commit();
            cp_wait<1>();      // B[r] landed; B[r+1] may be in flight
        } else {
            cp_wait<0>();
        }
        __syncthreads();

        uint32_t bufw = (uint32_t)(2 * TILE_WORDS + (r & 1) * 2 * TILE_WORDS);

        float acc[2][8][4];
        #pragma unroll
        for (int mt = 0; mt < 2; mt++)
            #pragma unroll
            for (int nt = 0; nt < 8; nt++)
                #pragma unroll
                for (int c = 0; c < 4; c++) acc[mt][nt][c] = 0.f;

        #pragma unroll
        for (int ks = 0; ks < 8; ks++) {
            uint32_t kw = (uint32_t)(ks * 8) * 4;
            uint32_t ah[2][4], al[2][4];
            ldsm_x4(ah[0], sbase + aoff * 4 + kw);
            ldsm_x4(ah[1], sbase + (aoff + 16 * APITCH) * 4 + kw);
            ldsm_x4(al[0], sbase + (TILE_WORDS + aoff) * 4 + kw);
            ldsm_x4(al[1], sbase + (TILE_WORDS + aoff + 16 * APITCH) * 4 + kw);
            uint32_t bh[8][2], bl[8][2];
            #pragma unroll
            for (int np = 0; np < 4; np++) {
                uint32_t r4[4];
                ldsm_x4(r4, sbase + (bufw + boff + np * 16 * APITCH) * 4 + kw);
                bh[np * 2][0] = r4[0]; bh[np * 2][1] = r4[1];
                bh[np * 2 + 1][0] = r4[2]; bh[np * 2 + 1][1] = r4[3];
                ldsm_x4(r4, sbase + (bufw + TILE_WORDS + boff + np * 16 * APITCH) * 4 + kw);
                bl[np * 2][0] = r4[0]; bl[np * 2][1] = r4[1];
                bl[np * 2 + 1][0] = r4[2]; bl[np * 2 + 1][1] = r4[3];
            }
            #pragma unroll
            for (int mt = 0; mt < 2; mt++)
                #pragma unroll
                for (int nt = 0; nt < 8; nt++) {
                    mma16816(acc[mt][nt], ah[mt], bh[nt]);
                    mma16816(acc[mt][nt], ah[mt], bl[nt]);
                    mma16816(acc[mt][nt], al[mt], bh[nt]);
                }
        }

        __half* outp = g_XWH + (size_t)r * Nn * F;
        #pragma unroll
        for (int mt = 0; mt < 2; mt++) {
            int row0 = rowBase + warpM * 32 + mt * 16 + g;
            int row1 = row0 + 8;
            #pragma unroll
            for (int nt = 0; nt < 8; nt++) {
                int col = warpN * 64 + nt * 8 + tig * 2;
                if (row0 < Nn) {
                    __half2 h = __floats2half2_rn(acc[mt][nt][0], acc[mt][nt][1]);
                    *(__half2*)(outp + (size_t)row0 * F + col) = h;
                }
                if (row1 < Nn) {
                    __half2 h = __floats2half2_rn(acc[mt][nt][2], acc[mt][nt][3]);
                    *(__half2*)(outp + (size_t)row1 * F + col) = h;
                }
            }
        }
    }
}

// -------- fused softmax + aggregate + bias(+relu) [+ next-layer split & logits] --------
__global__ __launch_bounds__(256) void fused_agg_kernel(float* __restrict__ outp,
                                                        const float* __restrict__ bias,
                                                        int layer, int relu, int donext,
                                                        int use2, int Nn) {
    __shared__ float swq[RELS * F];
    __shared__ float swk[RELS * F];
    __shared__ int   srow[8][WSLOTS];
    __shared__ float sex[8][WSLOTS];
    if (donext) {
        const float* WQ = g_WQ + (layer + 1) * RELS * F;
        const float* WK = g_WK + (layer + 1) * RELS * F;
        for (int i = threadIdx.x; i < RELS * F; i += blockDim.x) {
            swq[i] = WQ[i];
            swk[i] = WK[i];
        }
        __syncthreads();
    }

    int wslot = threadIdx.x >> 5;
    int node = (blockIdx.x * blockDim.x + threadIdx.x) >> 5;
    int lane = threadIdx.x & 31;
    if (node >= Nn) return;

    const float* NQ = use2 ? g_NQ2 : g_NQ;
    const float* NK = use2 ? g_NK2 : g_NK;

    int start = g_ROWPTR[node];
    int end   = g_ROWPTR[node + 1];
    float ce  = g_CE[layer];
    float nq0 = NQ[node * RELS + 0];
    float nq1 = NQ[node * RELS + 1];
    float nq2 = NQ[node * RELS + 2];

    float denom = 0.f;
    for (int i = start + lane; i < end; i += 32) {
        int4 e = g_EDGE[i];
        int t = e.x - (e.x / RELS) * RELS;
        float nq = (t == 0) ? nq0 : (t == 1) ? nq1 : nq2;
        float a = nq + NK[e.x] + ce * __int_as_float(e.z);
        a = (a > 0.f) ? a : 0.2f * a;
        float ex = expf(a);
        int k = i - start;
        if (k < WSLOTS) {
            srow[wslot][k] = e.y;
            sex[wslot][k]  = ex;
        } else {
            g_EX[i] = ex;
        }
        denom += ex;
    }
    #pragma unroll
    for (int off = 16; off; off >>= 1)
        denom += __shfl_xor_sync(0xffffffffu, denom, off);
    float inv = 1.f / (denom + 1e-16f);
    __syncwarp();

    int deg = end - start;
    int m = deg < WSLOTS ? deg : WSLOTS;
    float4 acc = make_float4(0.f, 0.f, 0.f, 0.f);
    int k = 0;
    for (; k + 7 < m; k += 8) {
        float at[8];
        uint2 u[8];
        #pragma unroll
        for (int u8 = 0; u8 < 8; u8++) {
            at[u8] = sex[wslot][k + u8] * inv;
            u[u8] = ((const uint2*)(g_XWH + (size_t)srow[wslot][k + u8] * F))[lane];
        }
        #pragma unroll
        for (int u8 = 0; u8 < 8; u8++) {
            float2 f0 = __half22float2(*(__half2*)&u[u8].x);
            float2 f1 = __half22float2(*(__half2*)&u[u8].y);
            acc.x += at[u8] * f0.x;
            acc.y += at[u8] * f0.y;
            acc.z += at[u8] * f1.x;
            acc.w += at[u8] * f1.y;
        }
    }
    for (; k + 3 < m; k += 4) {
        float at[4];
        uint2 u[4];
        #pragma unroll
        for (int u4 = 0; u4 < 4; u4++) {
            at[u4] = sex[wslot][k + u4] * inv;
            u[u4] = ((const uint2*)(g_XWH + (size_t)srow[wslot][k + u4] * F))[lane];
        }
        #pragma unroll
        for (int u4 = 0; u4 < 4; u4++) {
            float2 f0 = __half22float2(*(__half2*)&u[u4].x);
            float2 f1 = __half22float2(*(__half2*)&u[u4].y);
            acc.x += at[u4] * f0.x;
            acc.y += at[u4] * f0.y;
            acc.z += at[u4] * f1.x;
            acc.w += at[u4] * f1.y;
        }
    }
    for (; k < m; k++) {
        float at = sex[wslot][k] * inv;
        uint2 u = ((const uint2*)(g_XWH + (size_t)srow[wslot][k] * F))[lane];
        float2 f0 = __half22float2(*(__half2*)&u.x);
        float2 f1 = __half22float2(*(__half2*)&u.y);
        acc.x += at * f0.x;
        acc.y += at * f0.y;
        acc.z += at * f1.x;
        acc.w += at * f1.y;
    }
    for (int i = start + WSLOTS; i < end; i++) {
        float at = g_EX[i] * inv;
        int r0 = ((const int*)g_EDGE)[4 * i + 1];
        uint2 u = ((const uint2*)(g_XWH + (size_t)r0 * F))[lane];
        float2 f0 = __half22float2(*(__half2*)&u.x);
        float2 f1 = __half22float2(*(__half2*)&u.y);
        acc.x += at * f0.x;
        acc.y += at * f0.y;
        acc.z += at * f1.x;
        acc.w += at * f1.y;
    }

    const float4 b = *(const float4*)(bias + lane * 4);
    acc.x += b.x; acc.y += b.y; acc.z += b.z; acc.w += b.w;
    if (relu) {
        acc.x = acc.x > 0.f ? acc.x : 0.f;
        acc.y = acc.y > 0.f ? acc.y : 0.f;
        acc.z = acc.z > 0.f ? acc.z : 0.f;
        acc.w = acc.w > 0.f ? acc.w : 0.f;
    }
    *(float4*)(outp + (size_t)node * F + lane * 4) = acc;

    if (donext) {
        uint32_t* xh = g_XHI + (size_t)node * 64;
        uint32_t* xl = g_XLO + (size_t)node * 64;
        xh[lane * 2]     = pack_split_hi(acc.x, acc.y);
        xh[lane * 2 + 1] = pack_split_hi(acc.z, acc.w);
        xl[lane * 2]     = pack_split_lo(acc.x, acc.y);
        xl[lane * 2 + 1] = pack_split_lo(acc.z, acc.w);

        #pragma unroll
        for (int r = 0; r < RELS; r++) {
            const float4 q4 = ((const float4*)(swq + r * F))[lane];
            const float4 k4 = ((const float4*)(swk + r * F))[lane];
            float sq = acc.x * q4.x + acc.y * q4.y + acc.z * q4.z + acc.w * q4.w;
            float sk = acc.x * k4.x + acc.y * k4.y + acc.z * k4.z + acc.w * k4.w;
            #pragma unroll
            for (int off = 16; off; off >>= 1) {
                sq += __shfl_down_sync(0xffffffffu, sq, off);
                sk += __shfl_down_sync(0xffffffffu, sk, off);
            }
            if (lane == 0) {
                g_NQ2[node * RELS + r] = sq;
                g_NK2[node * RELS + r] = sk;
            }
        }
    }
}

// ---------------- launch ----------------
extern "C" void kernel_launch(void* const* d_in, const int* in_sizes, int n_in,
                              void* d_out, int out_size) {
    const float* x   = (const float*)d_in[0];
    const int*   ei  = (const int*)d_in[1];
    const int*   et  = (const int*)d_in[2];
    const float* ea  = (const float*)d_in[3];
    const float* w1  = (const float*)d_in[4];
    const float* q1  = (const float*)d_in[5];
    const float* k1  = (const float*)d_in[6];
    const float* e1  = (const float*)d_in[7];
    const float* we1 = (const float*)d_in[8];
    const float* b1  = (const float*)d_in[9];
    const float* w2  = (const float*)d_in[10];
    const float* q2  = (const float*)d_in[11];
    const float* k2  = (const float*)d_in[12];
    const float* e2  = (const float*)d_in[13];
    const float* we2 = (const float*)d_in[14];
    const float* b2  = (const float*)d_in[15];

    int Nn = in_sizes[0] / F;
    int Ecnt = in_sizes[2];
    const int* srcp = ei;
    const int* dstp = ei + Ecnt;
    float* outp = (float*)d_out;

    int setupThreads = N_PREP + N_PREPW + Nn;
    int edgeBlocks  = (Ecnt + 255) / 256;
    int scanBlocks  = (Nn + 255) / 256;
    int gemmBlocks  = (Nn + 127) / 128;
    int warpNodeBlk = (Nn + 7) / 8;

    cudaFuncSetAttribute(gemm_mma_kernel, cudaFuncAttributeMaxDynamicSharedMemorySize,
                         GEMM_SMEM_TOTAL);

    void* hptr = nullptr;
    cudaGetSymbolAddress(&hptr, g_H);

    setup_kernel<<<(setupThreads + 255) / 256, 256>>>(w1, q1, k1, w2, q2, k2,
                                                      we1, e1, we2, e2, Nn);         // 0
    split_nqnk_kernel<<<warpNodeBlk, 256>>>(x, Nn);                                  // 1
    hist_kernel<<<edgeBlocks, 256>>>(dstp, Ecnt);                                    // 2
    gemm_mma_kernel<<<gemmBlocks, 256, GEMM_SMEM_TOTAL>>>(0, Nn);                    // 3 (ncu window)
    scan1_kernel<<<scanBlocks, 256>>>(Nn);                                           // 4
    scan2_kernel<<<1, 1024>>>(scanBlocks);                                           // 5
    scan3_kernel<<<(Nn + 256) / 256, 256>>>(Nn, Ecnt);                               // 6
    scatter_kernel<<<edgeBlocks, 256>>>(srcp, dstp, et, ea, Ecnt, Nn);               // 7
    fused_agg_kernel<<<warpNodeBlk, 256>>>((float*)hptr, b1, 0, 1, 1, 0, Nn);        // 8
    gemm_mma_kernel<<<gemmBlocks, 256, GEMM_SMEM_TOTAL>>>(1, Nn);                    // 9
    fused_agg_kernel<<<warpNodeBlk, 256>>>(outp, b2, 1, 0, 0, 1, Nn);                // 10

    (void)n_in; (void)out_size;
}

// round 17
// speedup vs baseline: 1.1448x; 1.0402x over previous
#include <cuda_runtime.h>
#include <cuda_bf16.h>
#include <cuda_fp16.h>
#include <cstdint>

#define RELS 3
#define F 128
#define NMAX 50000
#define EMAX 800000
#define WSLOTS 64

// ---------------- scratch (static device globals; no allocation) ----------------
__device__ __half   g_XWH[(size_t)RELS * NMAX * F];  // [r][n][f] fp16, 38.4 MB (L2-resident)
__device__ float    g_H[(size_t)NMAX * F];
__device__ uint32_t g_XHI[(size_t)NMAX * 64];
__device__ uint32_t g_XLO[(size_t)NMAX * 64];
__device__ uint32_t g_WHI[2 * RELS * 128 * 64];
__device__ uint32_t g_WLO[2 * RELS * 128 * 64];
__device__ float    g_NQ[NMAX * RELS];
__device__ float    g_NK[NMAX * RELS];
__device__ float    g_NQ2[NMAX * RELS];
__device__ float    g_NK2[NMAX * RELS];
__device__ float    g_EX[EMAX];
__device__ float    g_WQ[2 * RELS * F];
__device__ float    g_WK[2 * RELS * F];
__device__ float    g_CE[2];
__device__ int   g_CNT[NMAX];
__device__ int   g_ROWPTR[NMAX + 1];
__device__ int   g_PART[NMAX];
__device__ int   g_BSUM[1024];
__device__ int4  g_EDGE[EMAX];                       // {nkidx, rowidx, sea_bits, 0}

__device__ __forceinline__ uint32_t pack_split_hi(float x, float y) {
    __nv_bfloat16 hx = __float2bfloat16_rn(x);
    __nv_bfloat16 hy = __float2bfloat16_rn(y);
    return ((uint32_t)*(uint16_t*)&hy << 16) | (uint32_t)*(uint16_t*)&hx;
}
__device__ __forceinline__ uint32_t pack_split_lo(float x, float y) {
    __nv_bfloat16 hx = __float2bfloat16_rn(x);
    __nv_bfloat16 hy = __float2bfloat16_rn(y);
    __nv_bfloat16 lx = __float2bfloat16_rn(x - __bfloat162float(hx));
    __nv_bfloat16 ly = __float2bfloat16_rn(y - __bfloat162float(hy));
    return ((uint32_t)*(uint16_t*)&ly << 16) | (uint32_t)*(uint16_t*)&lx;
}

// -------- setup: prep (wq/wk/ce) + prepw (W split) + zero_cnt, fused --------
#define N_PREP (4 * RELS * F + 2)
#define N_PREPW (2 * RELS * 64 * 128)
__global__ void setup_kernel(const float* __restrict__ w1, const float* __restrict__ q1,
                             const float* __restrict__ k1,
                             const float* __restrict__ w2, const float* __restrict__ q2,
                             const float* __restrict__ k2,
                             const float* __restrict__ we1, const float* __restrict__ e1,
                             const float* __restrict__ we2, const float* __restrict__ e2,
                             int Nn) {
    int idx = blockIdx.x * blockDim.x + threadIdx.x;
    if (idx < 4 * RELS * F) {
        int which = idx / (RELS * F);
        int rem   = idx % (RELS * F);
        const float* w = (which < 2) ? w1 : w2;
        const float* v = (which == 0) ? q1 : (which == 1) ? k1 : (which == 2) ? q2 : k2;
        const float* row = w + (size_t)rem * F;
        float s = 0.f;
        #pragma unroll 8
        for (int o = 0; o < F; o++) s += row[o] * v[o];
        float* d = (which == 0) ? g_WQ
                 : (which == 1) ? g_WK
                 : (which == 2) ? (g_WQ + RELS * F)
                 : (g_WK + RELS * F);
        d[rem] = s;
    } else if (idx == 4 * RELS * F) {
        float s = 0.f;
        for (int o = 0; o < F; o++) s += we1[o] * e1[o];
        g_CE[0] = s;
    } else if (idx == 4 * RELS * F + 1) {
        float s = 0.f;
        for (int o = 0; o < F; o++) s += we2[o] * e2[o];
        g_CE[1] = s;
    } else if (idx < N_PREP + N_PREPW) {
        int j = idx - N_PREP;
        int n     = j & 127;
        int p     = (j >> 7) & 63;
        int r     = (j >> 13) % RELS;
        int layer = j / (RELS * 64 * 128);
        const float* W = (layer == 0) ? w1 : w2;
        const float* Wr = W + (size_t)r * F * F;
        float vx = Wr[(size_t)(2 * p) * F + n];
        float vy = Wr[(size_t)(2 * p + 1) * F + n];
        size_t o = ((size_t)(layer * RELS + r) * 128 + n) * 64 + p;
        g_WHI[o] = pack_split_hi(vx, vy);
        g_WLO[o] = pack_split_lo(vx, vy);
    } else if (idx < N_PREP + N_PREPW + Nn) {
        g_CNT[idx - N_PREP - N_PREPW] = 0;
    }
}

// ---------------- CSR build ----------------
__global__ void hist_kernel(const int* __restrict__ dst, int Ecnt) {
    int e = blockIdx.x * blockDim.x + threadIdx.x;
    if (e < Ecnt) atomicAdd(&g_CNT[dst[e]], 1);
}
__global__ void scan1_kernel(int Nn) {
    __shared__ int sh[256];
    int i = blockIdx.x * 256 + threadIdx.x;
    int v = (i < Nn) ? g_CNT[i] : 0;
    sh[threadIdx.x] = v;
    __syncthreads();
    #pragma unroll
    for (int off = 1; off < 256; off <<= 1) {
        int t = (threadIdx.x >= off) ? sh[threadIdx.x - off] : 0;
        __syncthreads();
        sh[threadIdx.x] += t;
        __syncthreads();
    }
    if (i < Nn) g_PART[i] = sh[threadIdx.x] - v;
    if (threadIdx.x == 255) g_BSUM[blockIdx.x] = sh[255];
}
__global__ void scan2_kernel(int nb) {
    __shared__ int sh[1024];
    int v = (threadIdx.x < nb) ? g_BSUM[threadIdx.x] : 0;
    sh[threadIdx.x] = v;
    __syncthreads();
    #pragma unroll
    for (int off = 1; off < 1024; off <<= 1) {
        int t = (threadIdx.x >= off) ? sh[threadIdx.x - off] : 0;
        __syncthreads();
        sh[threadIdx.x] += t;
        __syncthreads();
    }
    if (threadIdx.x < nb) g_BSUM[threadIdx.x] = sh[threadIdx.x] - v;
}
__global__ void scan3_kernel(int Nn, int Ecnt) {
    int i = blockIdx.x * blockDim.x + threadIdx.x;
    if (i < Nn) {
        g_ROWPTR[i] = g_PART[i] + g_BSUM[i >> 8];
        g_CNT[i] = 0;
    }
    if (i == Nn) g_ROWPTR[Nn] = Ecnt;
}
__global__ void scatter_kernel(const int* __restrict__ src, const int* __restrict__ dst,
                               const int* __restrict__ et, const float* __restrict__ ea,
                               int Ecnt, int Nn) {
    int e = blockIdx.x * blockDim.x + threadIdx.x;
    if (e >= Ecnt) return;
    int d = dst[e];
    int pos = g_ROWPTR[d] + atomicAdd(&g_CNT[d], 1);
    int s = src[e], t = et[e];
    g_EDGE[pos] = make_int4(s * RELS + t, t * Nn + s, __float_as_int(ea[e]), 0);
}

// ------- fused: x -> bf16 hi/lo split + layer-1 attention logits; warp per node -------
__global__ __launch_bounds__(256) void split_nqnk_kernel(const float* __restrict__ xin, int Nn) {
    __shared__ float swq[RELS * F];
    __shared__ float swk[RELS * F];
    for (int i = threadIdx.x; i < RELS * F; i += blockDim.x) {
        swq[i] = g_WQ[i];
        swk[i] = g_WK[i];
    }
    __syncthreads();

    int warp = (blockIdx.x * blockDim.x + threadIdx.x) >> 5;
    int lane = threadIdx.x & 31;
    if (warp >= Nn) return;

    float4 v = ((const float4*)(xin + (size_t)warp * F))[lane];

    uint32_t* xh = g_XHI + (size_t)warp * 64;
    uint32_t* xl = g_XLO + (size_t)warp * 64;
    xh[lane * 2]     = pack_split_hi(v.x, v.y);
    xh[lane * 2 + 1] = pack_split_hi(v.z, v.w);
    xl[lane * 2]     = pack_split_lo(v.x, v.y);
    xl[lane * 2 + 1] = pack_split_lo(v.z, v.w);

    #pragma unroll
    for (int r = 0; r < RELS; r++) {
        const float4 q4 = ((const float4*)(swq + r * F))[lane];
        const float4 k4 = ((const float4*)(swk + r * F))[lane];
        float sq = v.x * q4.x + v.y * q4.y + v.z * q4.z + v.w * q4.w;
        float sk = v.x * k4.x + v.y * k4.y + v.z * k4.z + v.w * k4.w;
        #pragma unroll
        for (int off = 16; off; off >>= 1) {
            sq += __shfl_down_sync(0xffffffffu, sq, off);
            sk += __shfl_down_sync(0xffffffffu, sk, off);
        }
        if (lane == 0) {
            g_NQ[warp * RELS + r] = sq;
            g_NK[warp * RELS + r] = sk;
        }
    }
}

// == mma.sync bf16 GEMM: M=128, 8 warps 32x64, ldmatrix, cp.async dbuf B ==
// fp16 output staged through smem for coalesced uint4 stores.
#define APITCH 68
#define TILE_WORDS (128 * APITCH)
#define SPITCH 65                                // staging pitch (words) to avoid conflicts
#define GEMM_SMEM_TOTAL (6 * TILE_WORDS * 4)     // A hi/lo + 2x (B hi/lo); staging reuses B

__device__ __forceinline__ void mma16816(float* d, const uint32_t* a, const uint32_t* b) {
    asm volatile("mma.sync.aligned.m16n8k16.row.col.f32.bf16.bf16.f32 "
                 "{%0,%1,%2,%3}, {%4,%5,%6,%7}, {%8,%9}, {%0,%1,%2,%3};"
                 : "+f"(d[0]), "+f"(d[1]), "+f"(d[2]), "+f"(d[3])
                 : "r"(a[0]), "r"(a[1]), "r"(a[2]), "r"(a[3]), "r"(b[0]), "r"(b[1]));
}
__device__ __forceinline__ void ldsm_x4(uint32_t* r, uint32_t saddr) {
    asm volatile("ldmatrix.sync.aligned.m8n8.x4.shared.b16 {%0,%1,%2,%3}, [%4];"
                 : "=r"(r[0]), "=r"(r[1]), "=r"(r[2]), "=r"(r[3]) : "r"(saddr));
}
__device__ __forceinline__ void cp16(uint32_t dst_smem, const void* src) {
    asm volatile("cp.async.cg.shared.global [%0], [%1], 16;" :: "r"(dst_smem), "l"(src) : "memory");
}
__device__ __forceinline__ void cp_commit() {
    asm volatile("cp.async.commit_group;" ::: "memory");
}
template <int N>
__device__ __forceinline__ void cp_wait() {
    asm volatile("cp.async.wait_group %0;" :: "n"(N) : "memory");
}

__global__ __launch_bounds__(256) void gemm_mma_kernel(int layer, int Nn) {
    extern __shared__ uint32_t smem[];
    uint32_t* sAhi = smem;
    uint32_t* sAlo = smem + TILE_WORDS;

    int rowBase = blockIdx.x * 128;
    int tid = threadIdx.x;
    uint32_t sbase = (uint32_t)__cvta_generic_to_shared(smem);

    // ---- A tiles: loaded ONCE, reused for all 3 relations ----
    for (int idx = tid; idx < 128 * 64; idx += 256) {
        int row = idx >> 6;
        int pair = idx & 63;
        int grow = rowBase + row;
        uint32_t hi = 0, lo = 0;
        if (grow < Nn) {
            hi = g_XHI[(size_t)grow * 64 + pair];
            lo = g_XLO[(size_t)grow * 64 + pair];
        }
        sAhi[row * APITCH + pair] = hi;
        sAlo[row * APITCH + pair] = lo;
    }

    // ---- prefetch B[r=0] into buf0 via cp.async ----
    {
        const uint32_t* wh = g_WHI + (size_t)(layer * RELS) * 128 * 64;
        const uint32_t* wl = g_WLO + (size_t)(layer * RELS) * 128 * 64;
        uint32_t bhi = sbase + (2 * TILE_WORDS) * 4;
        uint32_t blo = sbase + (3 * TILE_WORDS) * 4;
        #pragma unroll
        for (int it = 0; it < 8; it++) {
            int c = tid + it * 256;
            int n = c >> 4;
            int p4 = (c & 15) * 4;
            uint32_t doff = (uint32_t)(n * APITCH + p4) * 4;
            cp16(bhi + doff, wh + n * 64 + p4);
            cp16(blo + doff, wl + n * 64 + p4);
        }
        cp_commit();
    }

    int wid = tid >> 5;
    int lane = tid & 31;
    int warpM = wid & 3;
    int warpN = wid >> 2;
    int g = lane >> 2;
    int tig = lane & 3;
    int rw = lane & 7;
    int quad = lane >> 3;

    uint32_t aoff = (uint32_t)((warpM * 32 + rw + (quad & 1) * 8) * APITCH + (quad >> 1) * 4);
    uint32_t boff = (uint32_t)((warpN * 64 + rw + (quad >> 1) * 8) * APITCH + (quad & 1) * 4);

    for (int r = 0; r < RELS; r++) {
        __syncthreads();   // staging copy-out of r-1 done; prefetch target free; A visible on r=0
        if (r + 1 < RELS) {
            const uint32_t* wh = g_WHI + (size_t)(layer * RELS + r + 1) * 128 * 64;
            const uint32_t* wl = g_WLO + (size_t)(layer * RELS + r + 1) * 128 * 64;
            uint32_t bhi = sbase + (2 * TILE_WORDS + ((r + 1) & 1) * 2 * TILE_WORDS) * 4;
            uint32_t blo = bhi + TILE_WORDS * 4;
            #pragma unroll
            for (int it = 0; it < 8; it++) {
                int c = tid + it * 256;
                int n = c >> 4;
                int p4 = (c & 15) * 4;
                uint32_t doff = (uint32_t)(n * APITCH + p4) * 4;
                cp16(bhi + doff, wh + n * 64 + p4);
                cp16(blo + doff, wl + n * 64 + p4);
            }
            cp_commit();
            cp_wait<1>();      // B[r] landed; B[r+1] may be in flight
        } else {
            cp_wait<0>();
        }
        __syncthreads();

        uint32_t bufw = (uint32_t)(2 * TILE_WORDS + (r & 1) * 2 * TILE_WORDS);

        float acc[2][8][4];
        #pragma unroll
        for (int mt = 0; mt < 2; mt++)
            #pragma unroll
            for (int nt = 0; nt < 8; nt++)
                #pragma unroll
                for (int c = 0; c < 4; c++) acc[mt][nt][c] = 0.f;

        #pragma unroll
        for (int ks = 0; ks < 8; ks++) {
            uint32_t kw = (uint32_t)(ks * 8) * 4;
            uint32_t ah[2][4], al[2][4];
            ldsm_x4(ah[0], sbase + aoff * 4 + kw);
            ldsm_x4(ah[1], sbase + (aoff + 16 * APITCH) * 4 + kw);
            ldsm_x4(al[0], sbase + (TILE_WORDS + aoff) * 4 + kw);
            ldsm_x4(al[1], sbase + (TILE_WORDS + aoff + 16 * APITCH) * 4 + kw);
            uint32_t bh[8][2], bl[8][2];
            #pragma unroll
            for (int np = 0; np < 4; np++) {
                uint32_t r4[4];
                ldsm_x4(r4, sbase + (bufw + boff + np * 16 * APITCH) * 4 + kw);
                bh[np * 2][0] = r4[0]; bh[np * 2][1] = r4[1];
                bh[np * 2 + 1][0] = r4[2]; bh[np * 2 + 1][1] = r4[3];
                ldsm_x4(r4, sbase + (bufw + TILE_WORDS + boff + np * 16 * APITCH) * 4 + kw);
                bl[np * 2][0] = r4[0]; bl[np * 2][1] = r4[1];
                bl[np * 2 + 1][0] = r4[2]; bl[np * 2 + 1][1] = r4[3];
            }
            #pragma unroll
            for (int mt = 0; mt < 2; mt++)
                #pragma unroll
                for (int nt = 0; nt < 8; nt++) {
                    mma16816(acc[mt][nt], ah[mt], bh[nt]);
                    mma16816(acc[mt][nt], ah[mt], bl[nt]);
                    mma16816(acc[mt][nt], al[mt], bh[nt]);
                }
        }

        // ---- epilogue: stage fp16 tile in the just-consumed B buffer, then
        //      stream out with coalesced uint4 stores ----
        __syncthreads();                          // all warps done reading B[r]
        uint32_t* stage = smem + bufw;            // 128 rows x SPITCH words (8320 <= 8704)
        #pragma unroll
        for (int mt = 0; mt < 2; mt++) {
            int brow0 = warpM * 32 + mt * 16 + g;
            int brow1 = brow0 + 8;
            #pragma unroll
            for (int nt = 0; nt < 8; nt++) {
                int cw = (warpN * 64 + nt * 8 + tig * 2) >> 1;   // column word index
                __half2 h0 = __floats2half2_rn(acc[mt][nt][0], acc[mt][nt][1]);
                __half2 h1 = __floats2half2_rn(acc[mt][nt][2], acc[mt][nt][3]);
                stage[brow0 * SPITCH + cw] = *(uint32_t*)&h0;
                stage[brow1 * SPITCH + cw] = *(uint32_t*)&h1;
            }
        }
        __syncthreads();
        __half* outp = g_XWH + (size_t)r * Nn * F;
        #pragma unroll
        for (int it = 0; it < 8; it++) {
            int c = tid + it * 256;               // 16B-chunk index, 0..2047
            int row = c >> 4;
            int w4 = (c & 15) * 4;
            int grow = rowBase + row;
            if (grow < Nn) {
                uint4 v;
                const uint32_t* s = stage + row * SPITCH + w4;
                v.x = s[0]; v.y = s[1]; v.z = s[2]; v.w = s[3];
                *(uint4*)(outp + (size_t)grow * F + w4 * 2) = v;
            }
        }
    }
}

// -------- fused softmax + aggregate + bias(+relu) [+ next-layer split & logits] --------
__global__ __launch_bounds__(256) void fused_agg_kernel(float* __restrict__ outp,
                                                        const float* __restrict__ bias,
                                                        int layer, int relu, int donext,
                                                        int use2, int Nn) {
    __shared__ float swq[RELS * F];
    __shared__ float swk[RELS * F];
    __shared__ int   srow[8][WSLOTS];
    __shared__ float sex[8][WSLOTS];
    if (donext) {
        const float* WQ = g_WQ + (layer + 1) * RELS * F;
        const float* WK = g_WK + (layer + 1) * RELS * F;
        for (int i = threadIdx.x; i < RELS * F; i += blockDim.x) {
            swq[i] = WQ[i];
            swk[i] = WK[i];
        }
        __syncthreads();
    }

    int wslot = threadIdx.x >> 5;
    int node = (blockIdx.x * blockDim.x + threadIdx.x) >> 5;
    int lane = threadIdx.x & 31;
    if (node >= Nn) return;

    const float* NQ = use2 ? g_NQ2 : g_NQ;
    const float* NK = use2 ? g_NK2 : g_NK;

    int start = g_ROWPTR[node];
    int end   = g_ROWPTR[node + 1];
    float ce  = g_CE[layer];
    float nq0 = NQ[node * RELS + 0];
    float nq1 = NQ[node * RELS + 1];
    float nq2 = NQ[node * RELS + 2];

    float denom = 0.f;
    for (int i = start + lane; i < end; i += 32) {
        int4 e = g_EDGE[i];
        int t = e.x - (e.x / RELS) * RELS;
        float nq = (t == 0) ? nq0 : (t == 1) ? nq1 : nq2;
        float a = nq + NK[e.x] + ce * __int_as_float(e.z);
        a = (a > 0.f) ? a : 0.2f * a;
        float ex = expf(a);
        int k = i - start;
        if (k < WSLOTS) {
            srow[wslot][k] = e.y;
            sex[wslot][k]  = ex;
        } else {
            g_EX[i] = ex;
        }
        denom += ex;
    }
    #pragma unroll
    for (int off = 16; off; off >>= 1)
        denom += __shfl_xor_sync(0xffffffffu, denom, off);
    float inv = 1.f / (denom + 1e-16f);
    __syncwarp();

    int deg = end - start;
    int m = deg < WSLOTS ? deg : WSLOTS;
    float4 acc = make_float4(0.f, 0.f, 0.f, 0.f);
    int k = 0;
    for (; k + 7 < m; k += 8) {
        float at[8];
        uint2 u[8];
        #pragma unroll
        for (int u8 = 0; u8 < 8; u8++) {
            at[u8] = sex[wslot][k + u8] * inv;
            u[u8] = ((const uint2*)(g_XWH + (size_t)srow[wslot][k + u8] * F))[lane];
        }
        #pragma unroll
        for (int u8 = 0; u8 < 8; u8++) {
            float2 f0 = __half22float2(*(__half2*)&u[u8].x);
            float2 f1 = __half22float2(*(__half2*)&u[u8].y);
            acc.x += at[u8] * f0.x;
            acc.y += at[u8] * f0.y;
            acc.z += at[u8] * f1.x;
            acc.w += at[u8] * f1.y;
        }
    }
    for (; k + 3 < m; k += 4) {
        float at[4];
        uint2 u[4];
        #pragma unroll
        for (int u4 = 0; u4 < 4; u4++) {
            at[u4] = sex[wslot][k + u4] * inv;
            u[u4] = ((const uint2*)(g_XWH + (size_t)srow[wslot][k + u4] * F))[lane];
        }
        #pragma unroll
        for (int u4 = 0; u4 < 4; u4++) {
            float2 f0 = __half22float2(*(__half2*)&u[u4].x);
            float2 f1 = __half22float2(*(__half2*)&u[u4].y);
            acc.x += at[u4] * f0.x;
            acc.y += at[u4] * f0.y;
            acc.z += at[u4] * f1.x;
            acc.w += at[u4] * f1.y;
        }
    }
    for (; k < m; k++) {
        float at = sex[wslot][k] * inv;
        uint2 u = ((const uint2*)(g_XWH + (size_t)srow[wslot][k] * F))[lane];
        float2 f0 = __half22float2(*(__half2*)&u.x);
        float2 f1 = __half22float2(*(__half2*)&u.y);
        acc.x += at * f0.x;
        acc.y += at * f0.y;
        acc.z += at * f1.x;
        acc.w += at * f1.y;
    }
    for (int i = start + WSLOTS; i < end; i++) {
        float at = g_EX[i] * inv;
        int r0 = ((const int*)g_EDGE)[4 * i + 1];
        uint2 u = ((const uint2*)(g_XWH + (size_t)r0 * F))[lane];
        float2 f0 = __half22float2(*(__half2*)&u.x);
        float2 f1 = __half22float2(*(__half2*)&u.y);
        acc.x += at * f0.x;
        acc.y += at * f0.y;
        acc.z += at * f1.x;
        acc.w += at * f1.y;
    }

    const float4 b = *(const float4*)(bias + lane * 4);
    acc.x += b.x; acc.y += b.y; acc.z += b.z; acc.w += b.w;
    if (relu) {
        acc.x = acc.x > 0.f ? acc.x : 0.f;
        acc.y = acc.y > 0.f ? acc.y : 0.f;
        acc.z = acc.z > 0.f ? acc.z : 0.f;
        acc.w = acc.w > 0.f ? acc.w : 0.f;
    }
    *(float4*)(outp + (size_t)node * F + lane * 4) = acc;

    if (donext) {
        uint32_t* xh = g_XHI + (size_t)node * 64;
        uint32_t* xl = g_XLO + (size_t)node * 64;
        xh[lane * 2]     = pack_split_hi(acc.x, acc.y);
        xh[lane * 2 + 1] = pack_split_hi(acc.z, acc.w);
        xl[lane * 2]     = pack_split_lo(acc.x, acc.y);
        xl[lane * 2 + 1] = pack_split_lo(acc.z, acc.w);

        #pragma unroll
        for (int r = 0; r < RELS; r++) {
            const float4 q4 = ((const float4*)(swq + r * F))[lane];
            const float4 k4 = ((const float4*)(swk + r * F))[lane];
            float sq = acc.x * q4.x + acc.y * q4.y + acc.z * q4.z + acc.w * q4.w;
            float sk = acc.x * k4.x + acc.y * k4.y + acc.z * k4.z + acc.w * k4.w;
            #pragma unroll
            for (int off = 16; off; off >>= 1) {
                sq += __shfl_down_sync(0xffffffffu, sq, off);
                sk += __shfl_down_sync(0xffffffffu, sk, off);
            }
            if (lane == 0) {
                g_NQ2[node * RELS + r] = sq;
                g_NK2[node * RELS + r] = sk;
            }
        }
    }
}

// ---------------- launch ----------------
extern "C" void kernel_launch(void* const* d_in, const int* in_sizes, int n_in,
                              void* d_out, int out_size) {
    const float* x   = (const float*)d_in[0];
    const int*   ei  = (const int*)d_in[1];
    const int*   et  = (const int*)d_in[2];
    const float* ea  = (const float*)d_in[3];
    const float* w1  = (const float*)d_in[4];
    const float* q1  = (const float*)d_in[5];
    const float* k1  = (const float*)d_in[6];
    const float* e1  = (const float*)d_in[7];
    const float* we1 = (const float*)d_in[8];
    const float* b1  = (const float*)d_in[9];
    const float* w2  = (const float*)d_in[10];
    const float* q2  = (const float*)d_in[11];
    const float* k2  = (const float*)d_in[12];
    const float* e2  = (const float*)d_in[13];
    const float* we2 = (const float*)d_in[14];
    const float* b2  = (const float*)d_in[15];

    int Nn = in_sizes[0] / F;
    int Ecnt = in_sizes[2];
    const int* srcp = ei;
    const int* dstp = ei + Ecnt;
    float* outp = (float*)d_out;

    int setupThreads = N_PREP + N_PREPW + Nn;
    int edgeBlocks  = (Ecnt + 255) / 256;
    int scanBlocks  = (Nn + 255) / 256;
    int gemmBlocks  = (Nn + 127) / 128;
    int warpNodeBlk = (Nn + 7) / 8;

    cudaFuncSetAttribute(gemm_mma_kernel, cudaFuncAttributeMaxDynamicSharedMemorySize,
                         GEMM_SMEM_TOTAL);

    void* hptr = nullptr;
    cudaGetSymbolAddress(&hptr, g_H);

    setup_kernel<<<(setupThreads + 255) / 256, 256>>>(w1, q1, k1, w2, q2, k2,
                                                      we1, e1, we2, e2, Nn);         // 0
    split_nqnk_kernel<<<warpNodeBlk, 256>>>(x, Nn);                                  // 1
    hist_kernel<<<edgeBlocks, 256>>>(dstp, Ecnt);                                    // 2
    gemm_mma_kernel<<<gemmBlocks, 256, GEMM_SMEM_TOTAL>>>(0, Nn);                    // 3 (ncu window)
    scan1_kernel<<<scanBlocks, 256>>>(Nn);                                           // 4
    scan2_kernel<<<1, 1024>>>(scanBlocks);                                           // 5
    scan3_kernel<<<(Nn + 256) / 256, 256>>>(Nn, Ecnt);                               // 6
    scatter_kernel<<<edgeBlocks, 256>>>(srcp, dstp, et, ea, Ecnt, Nn);               // 7
    fused_agg_kernel<<<warpNodeBlk, 256>>>((float*)hptr, b1, 0, 1, 1, 0, Nn);        // 8
    gemm_mma_kernel<<<gemmBlocks, 256, GEMM_SMEM_TOTAL>>>(1, Nn);                    // 9
    fused_agg_kernel<<<warpNodeBlk, 256>>>(outp, b2, 1, 0, 0, 1, Nn);                // 10

    (void)n_in; (void)out_size;
}